// round 8
// baseline (speedup 1.0000x reference)
#include <cuda_runtime.h>

#define BATCH 4096
#define NCLS  10000
#define DIM   256
#define ALPHA 0.5f
#define CAP   64   // per-class row-list capacity (overflow handled exactly)

// Scratch (allocation-free: __device__ globals).
// g_cnt starts zeroed (static init) and is RESTORED to zero by
// scale_gather_kernel (lane 0, program order) -> no zero kernel needed.
__device__ int g_cnt[NCLS];         // per-class sample count
__device__ int g_label[BATCH];      // decoded label per row (overflow fallback)
__device__ int g_rows[NCLS * CAP];  // per-class row index list (8B aligned rows)

// ---------------------------------------------------------------------------
// K1: one block per batch row.
//  a) prefetch feat[b*DIM+t] (label-independent) before the scan
//  b) early-exit scan of the onehot row, 8 KB chunks (2 float4/thread, MLP=2)
//  c) finder thread: record label, append row to class list, bump count
//  d) loss ||feat - centers[label]||^2; only the centers gather is on the
//     dependent tail now.
// ---------------------------------------------------------------------------
__global__ __launch_bounds__(256, 8)
void scan_loss_kernel(const float* __restrict__ onehot,
                      const float* __restrict__ feat,
                      const float* __restrict__ centers,
                      float* __restrict__ loss_out) {
    const int b = blockIdx.x;
    const int t = threadIdx.x;

    __shared__ int s_label;
    __shared__ float s_red[8];
    if (t == 0) s_label = -1;

    // prefetch: independent of label, issues before/with the first scan loads
    const float f = feat[(size_t)b * DIM + t];

    __syncthreads();

    const float4* row = reinterpret_cast<const float4*>(onehot + (size_t)b * NCLS);
    const int NV4 = NCLS / 4;  // 2500 float4s

    #pragma unroll 1
    for (int it = 0; it < (NV4 + 511) / 512; ++it) {
        const int i0 = it * 512 + t;
        const int i1 = i0 + 256;
        float4 v0 = make_float4(0.f, 0.f, 0.f, 0.f);
        float4 v1 = make_float4(0.f, 0.f, 0.f, 0.f);
        if (i0 < NV4) v0 = row[i0];          // both loads in flight (MLP=2)
        if (i1 < NV4) v1 = row[i1];
        int found = -1;
        if (v0.x != 0.f)      found = 4 * i0 + 0;
        else if (v0.y != 0.f) found = 4 * i0 + 1;
        else if (v0.z != 0.f) found = 4 * i0 + 2;
        else if (v0.w != 0.f) found = 4 * i0 + 3;
        else if (v1.x != 0.f) found = 4 * i1 + 0;
        else if (v1.y != 0.f) found = 4 * i1 + 1;
        else if (v1.z != 0.f) found = 4 * i1 + 2;
        else if (v1.w != 0.f) found = 4 * i1 + 3;
        if (found >= 0) {
            s_label = found;
            g_label[b] = found;
            int slot = atomicAdd(&g_cnt[found], 1);
            if (slot < CAP) g_rows[found * CAP + slot] = b;
        }
        __syncthreads();
        if (s_label >= 0) break;
    }

    const int label = s_label;

    // loss vs OLD centers (thread t owns dim t); only this gather is dependent
    float c = centers[(size_t)label * DIM + t];
    float d = f - c;
    float sq = d * d;
    #pragma unroll
    for (int off = 16; off > 0; off >>= 1)
        sq += __shfl_down_sync(0xFFFFFFFFu, sq, off);
    if ((t & 31) == 0) s_red[t >> 5] = sq;
    __syncthreads();
    if (t < 8) {
        float v = s_red[t];
        #pragma unroll
        for (int off = 4; off > 0; off >>= 1)
            v += __shfl_down_sync(0xFFu, v, off);
        if (t == 0) loss_out[b] = v;
    }
}

// ---------------------------------------------------------------------------
// K2: one WARP per class, 2 float4 per lane (DIM=256 -> 64 float4).
//   out = k*centers + s * sum(feat rows of class)   k=1-a*n/(n+1), s=a/(n+1)
// Lane 0 loads n + first two row slots (co-issued), zeroes g_cnt[c] in
// program order (only lane 0 ever reads it -> no barrier needed), and
// broadcasts via shfl (~26 cyc, vs a block-wide sync on DRAM latency).
// For n<=2 (99.4% of classes) all 4 feat gathers per thread are independent.
// ---------------------------------------------------------------------------
__global__ __launch_bounds__(256)
void scale_gather_kernel(const float* __restrict__ centers,
                         const float* __restrict__ feat,
                         float* __restrict__ out_centers) {
    const int warp = (blockIdx.x * blockDim.x + threadIdx.x) >> 5;
    if (warp >= NCLS) return;
    const int lane = threadIdx.x & 31;
    const int c = warp;

    // lane 0: meta loads (co-issued) + self-clean in program order
    int n_ = 0; int2 r01_ = make_int2(0, 0);
    if (lane == 0) {
        n_   = g_cnt[c];
        r01_ = *reinterpret_cast<const int2*>(&g_rows[c * CAP]);
        g_cnt[c] = 0;  // same thread that read it -> ordered, race-free
    }
    // centers loads issue independently of the meta chain
    const float4* crow = reinterpret_cast<const float4*>(centers + (size_t)c * DIM);
    float4 a0 = crow[lane];
    float4 a1 = crow[lane + 32];

    const int n  = __shfl_sync(0xFFFFFFFFu, n_, 0);
    const int r0 = __shfl_sync(0xFFFFFFFFu, r01_.x, 0);
    const int r1 = __shfl_sync(0xFFFFFFFFu, r01_.y, 0);

    const float fn = (float)n;
    const float k = 1.0f - ALPHA * fn / (fn + 1.0f);
    const float s = ALPHA / (fn + 1.0f);
    a0.x *= k; a0.y *= k; a0.z *= k; a0.w *= k;
    a1.x *= k; a1.y *= k; a1.z *= k; a1.w *= k;

    const float4* feat4 = reinterpret_cast<const float4*>(feat);

    if (n >= 1) {
        // up to 4 independent gathers in flight
        float4 f00 = feat4[(size_t)r0 * 64 + lane];
        float4 f01 = feat4[(size_t)r0 * 64 + lane + 32];
        float4 f10 = make_float4(0.f, 0.f, 0.f, 0.f);
        float4 f11 = make_float4(0.f, 0.f, 0.f, 0.f);
        if (n >= 2) {
            f10 = feat4[(size_t)r1 * 64 + lane];
            f11 = feat4[(size_t)r1 * 64 + lane + 32];
        }
        a0.x += s * (f00.x + f10.x); a0.y += s * (f00.y + f10.y);
        a0.z += s * (f00.z + f10.z); a0.w += s * (f00.w + f10.w);
        a1.x += s * (f01.x + f11.x); a1.y += s * (f01.y + f11.y);
        a1.z += s * (f01.z + f11.z); a1.w += s * (f01.w + f11.w);

        if (n > 2) {
            const int m = (n <= CAP) ? n : CAP;
            #pragma unroll 1
            for (int j = 2; j < m; ++j) {
                int bj = g_rows[c * CAP + j];
                float4 g0 = feat4[(size_t)bj * 64 + lane];
                float4 g1 = feat4[(size_t)bj * 64 + lane + 32];
                a0.x += s * g0.x; a0.y += s * g0.y; a0.z += s * g0.z; a0.w += s * g0.w;
                a1.x += s * g1.x; a1.y += s * g1.y; a1.z += s * g1.z; a1.w += s * g1.w;
            }
            if (n > CAP) {
                // exhaustive fallback (statistically unreachable; exact)
                #pragma unroll 1
                for (int bb = 0; bb < BATCH; ++bb) {
                    if (g_label[bb] == c) {
                        bool seen = false;
                        for (int j = 0; j < CAP; ++j)
                            if (g_rows[c * CAP + j] == bb) { seen = true; break; }
                        if (!seen) {
                            float4 g0 = feat4[(size_t)bb * 64 + lane];
                            float4 g1 = feat4[(size_t)bb * 64 + lane + 32];
                            a0.x += s * g0.x; a0.y += s * g0.y;
                            a0.z += s * g0.z; a0.w += s * g0.w;
                            a1.x += s * g1.x; a1.y += s * g1.y;
                            a1.z += s * g1.z; a1.w += s * g1.w;
                        }
                    }
                }
            }
        }
    }

    float4* orow = reinterpret_cast<float4*>(out_centers + (size_t)c * DIM);
    orow[lane]      = a0;
    orow[lane + 32] = a1;
}

// ---------------------------------------------------------------------------
extern "C" void kernel_launch(void* const* d_in, const int* in_sizes, int n_in,
                              void* d_out, int out_size) {
    const float* feat    = (const float*)d_in[0];  // [4096, 256]
    const float* onehot  = (const float*)d_in[1];  // [4096, 10000]
    const float* centers = (const float*)d_in[2];  // [10000, 256]

    float* loss_out    = (float*)d_out;            // [4096]
    float* centers_out = (float*)d_out + BATCH;    // [10000, 256]

    scan_loss_kernel<<<BATCH, 256>>>(onehot, feat, centers, loss_out);
    // 10000 classes, one warp each -> 1250 blocks of 256 threads
    scale_gather_kernel<<<(NCLS * 32 + 255) / 256, 256>>>(centers, feat, centers_out);
}